// round 12
// baseline (speedup 1.0000x reference)
#include <cuda_runtime.h>

#define N_CLASS   10
#define PSTRIDE   12
#define MAX_NODES 100000

typedef unsigned long long ull;

__device__ __align__(16) float g_P[MAX_NODES * PSTRIDE];
__device__ __align__(16) float g_Q[MAX_NODES * PSTRIDE];

// packed fp32x2 ops
#define FFMA2(acc, a, b) \
    asm("fma.rn.f32x2 %0, %1, %2, %0;" : "+l"(acc) : "l"(a), "l"(b))
#define FADD2(r, a, b) \
    asm("add.rn.f32x2 %0, %1, %2;" : "=l"(r) : "l"(a), "l"(b))

__device__ __forceinline__ ull pack2(float x, float y) {
    ull r;
    asm("mov.b64 %0, {%1, %2};" : "=l"(r) : "f"(x), "f"(y));
    return r;
}

// lane-resident weights: wp[p][k] = (W[2p][col], W[2p+1][col]) for this lane's 4 cols
__device__ __forceinline__ void load_weights(const float* __restrict__ W, int wcol,
                                             int lane, ull wp[5][4]) {
#pragma unroll
    for (int p = 0; p < 5; p++) {
        float4 wa = ((const float4*)(W + (2 * p) * 384 + wcol))[lane];
        float4 wb = ((const float4*)(W + (2 * p + 1) * 384 + wcol))[lane];
        wp[p][0] = pack2(wa.x, wb.x);
        wp[p][1] = pack2(wa.y, wb.y);
        wp[p][2] = pack2(wa.z, wb.z);
        wp[p][3] = pack2(wa.w, wb.w);
    }
}

__device__ __forceinline__ void dot10(const ull wp[5][4], float4 v, ull acc[5]) {
    ull a0 = pack2(v.x, v.x);
    ull a1 = pack2(v.y, v.y);
    ull a2 = pack2(v.z, v.z);
    ull a3 = pack2(v.w, v.w);
#pragma unroll
    for (int p = 0; p < 5; p++) {
        FFMA2(acc[p], a0, wp[p][0]);
        FFMA2(acc[p], a1, wp[p][1]);
        FFMA2(acc[p], a2, wp[p][2]);
        FFMA2(acc[p], a3, wp[p][3]);
    }
}

// Slot-ordered warp reduction, fully packed, zero selects.
// Slot A holds edge k=perm[octet]; B=k^1 (xor16 partner's keep-edge);
// C=k^2 (xor8 partner's); D=k^3. After this, every lane of octet o holds
// the complete 10-class result (5 packed pairs) of edge perm[o].
__device__ __forceinline__ void reduce_slots(const ull aA[5], const ull aB[5],
                                             const ull aC[5], const ull aD[5],
                                             ull u[5]) {
#pragma unroll
    for (int q = 0; q < 5; q++) {
        ull tA, tB, w;
        FADD2(tA, aA[q], __shfl_xor_sync(0xffffffffu, aB[q], 16));
        FADD2(tB, aC[q], __shfl_xor_sync(0xffffffffu, aD[q], 16));
        FADD2(w, tA, __shfl_xor_sync(0xffffffffu, tB, 8));
        FADD2(w, w, __shfl_xor_sync(0xffffffffu, w, 4));
        FADD2(w, w, __shfl_xor_sync(0xffffffffu, w, 2));
        FADD2(w, w, __shfl_xor_sync(0xffffffffu, w, 1));
        u[q] = w;
    }
}

// ---------------------------------------------------------------------------
// Fused node projection: first half of grid writes g_P (h@W1^T + b),
// second half writes g_Q (h@W2^T). Pipelined, packed epilogue.
// ---------------------------------------------------------------------------
__global__ __launch_bounds__(128)
void proj_kernel(const float* __restrict__ X, const float* __restrict__ W,
                 const float* __restrict__ bias, int n_rows) {
    int half = gridDim.x >> 1;
    int which = blockIdx.x >= half;
    int bx = which ? (blockIdx.x - half) : blockIdx.x;
    float* outbuf = which ? g_Q : g_P;
    int wcol = which ? 128 : 0;

    int lane = threadIdx.x & 31;
    int warp = (bx * blockDim.x + threadIdx.x) >> 5;
    int nwarps = (half * blockDim.x) >> 5;
    int o = lane >> 3, j = lane & 7;
    int k = ((o & 1) << 1) | (o >> 1);
    int kB = k ^ 1, kC = k ^ 2, kD = k ^ 3;
    int stride = nwarps * 4;

    ull wp[5][4];
    load_weights(W, wcol, lane, wp);

    ull bp0 = 0ull, bp1 = 0ull;
    if (!which && j < 3) {
        if (j < 2) {
            bp0 = pack2(__ldg(bias + 4 * j), __ldg(bias + 4 * j + 1));
            bp1 = pack2(__ldg(bias + 4 * j + 2), __ldg(bias + 4 * j + 3));
        } else {
            bp0 = pack2(__ldg(bias + 8), __ldg(bias + 9));
        }
    }

    const float4* Xv = (const float4*)X;
    int nm1 = n_rows - 1;
    int base = warp * 4;
    if (base >= n_rows) return;

    float4 vA = Xv[(size_t)min(base + k, nm1) * 32 + lane];
    float4 vB = Xv[(size_t)min(base + kB, nm1) * 32 + lane];
    float4 vC = Xv[(size_t)min(base + kC, nm1) * 32 + lane];
    float4 vD = Xv[(size_t)min(base + kD, nm1) * 32 + lane];

    while (true) {
        int nb = base + stride;
        bool has_next = nb < n_rows;
        float4 nA, nB, nC, nD;
        if (has_next) {
            nA = Xv[(size_t)min(nb + k, nm1) * 32 + lane];
            nB = Xv[(size_t)min(nb + kB, nm1) * 32 + lane];
            nC = Xv[(size_t)min(nb + kC, nm1) * 32 + lane];
            nD = Xv[(size_t)min(nb + kD, nm1) * 32 + lane];
        }

        ull aA[5], aB[5], aC[5], aD[5];
#pragma unroll
        for (int q = 0; q < 5; q++) { aA[q] = aB[q] = aC[q] = aD[q] = 0ull; }
        dot10(wp, vA, aA);
        dot10(wp, vB, aB);
        dot10(wp, vC, aC);
        dot10(wp, vD, aD);

        ull u[5];
        reduce_slots(aA, aB, aC, aD, u);

        int ridx = base + k;
        if (ridx < n_rows && j < 3) {
            ull* O = (ull*)(outbuf + (size_t)ridx * PSTRIDE);
            if (j == 0) {
                ull r0, r1;
                FADD2(r0, u[0], bp0);
                FADD2(r1, u[1], bp1);
                O[0] = r0; O[1] = r1;
            } else if (j == 1) {
                ull r0, r1;
                FADD2(r0, u[2], bp0);
                FADD2(r1, u[3], bp1);
                O[2] = r0; O[3] = r1;
            } else {
                ull r0;
                FADD2(r0, u[4], bp0);
                O[4] = r0;
            }
        }

        if (!has_next) break;
        base = nb;
        vA = nA; vB = nB; vC = nC; vD = nD;
    }
}

// ---------------------------------------------------------------------------
// Edge kernel: out[e] = eh[e] @ W[:,256:384]^T + P[src[e]] + Q[dst[e]]
// Pipelined; slot-ordered reduction; packed gather/store epilogue split
// across 3 lanes per octet.
// ---------------------------------------------------------------------------
__global__ __launch_bounds__(128)
void edge_score_kernel(const float* __restrict__ eh, const float* __restrict__ W,
                       const int* __restrict__ src, const int* __restrict__ dst,
                       float* __restrict__ out, int n_edges) {
    int lane = threadIdx.x & 31;
    int warp = (blockIdx.x * blockDim.x + threadIdx.x) >> 5;
    int nwarps = (gridDim.x * blockDim.x) >> 5;
    int o = lane >> 3, j = lane & 7;
    int k = ((o & 1) << 1) | (o >> 1);
    int kB = k ^ 1, kC = k ^ 2, kD = k ^ 3;
    int stride = nwarps * 4;

    ull wp[5][4];
    load_weights(W, 256, lane, wp);

    const float4* Ev = (const float4*)eh;
    int nm1 = n_edges - 1;
    int base = warp * 4;
    if (base >= n_edges) return;

    float4 vA = Ev[(size_t)min(base + k, nm1) * 32 + lane];
    float4 vB = Ev[(size_t)min(base + kB, nm1) * 32 + lane];
    float4 vC = Ev[(size_t)min(base + kC, nm1) * 32 + lane];
    float4 vD = Ev[(size_t)min(base + kD, nm1) * 32 + lane];
    int ce = min(base + k, nm1);
    int s = src[ce], d = dst[ce];            // broadcast within octet

    while (true) {
        int nb = base + stride;
        bool has_next = nb < n_edges;
        float4 nA, nB, nC, nD;
        int ns = 0, nd2 = 0;
        if (has_next) {
            nA = Ev[(size_t)min(nb + k, nm1) * 32 + lane];
            nB = Ev[(size_t)min(nb + kB, nm1) * 32 + lane];
            nC = Ev[(size_t)min(nb + kC, nm1) * 32 + lane];
            nD = Ev[(size_t)min(nb + kD, nm1) * 32 + lane];
            int ne = min(nb + k, nm1);
            ns = src[ne]; nd2 = dst[ne];
        }

        ull aA[5], aB[5], aC[5], aD[5];
#pragma unroll
        for (int q = 0; q < 5; q++) { aA[q] = aB[q] = aC[q] = aD[q] = 0ull; }
        dot10(wp, vA, aA);
        dot10(wp, vB, aB);
        dot10(wp, vC, aC);
        dot10(wp, vD, aD);

        ull u[5];
        reduce_slots(aA, aB, aC, aD, u);

        int eidx = base + k;
        if (eidx < n_edges && j < 3) {
            const float* Pb = g_P + (size_t)s * PSTRIDE;
            const float* Qb = g_Q + (size_t)d * PSTRIDE;
            ull* ob = (ull*)(out + (size_t)eidx * N_CLASS);
            if (j == 0) {
                ulonglong2 P = *(const ulonglong2*)Pb;
                ulonglong2 Q = *(const ulonglong2*)Qb;
                ull r0, r1;
                FADD2(r0, u[0], P.x); FADD2(r0, r0, Q.x);
                FADD2(r1, u[1], P.y); FADD2(r1, r1, Q.y);
                ob[0] = r0; ob[1] = r1;
            } else if (j == 1) {
                ulonglong2 P = *(const ulonglong2*)(Pb + 4);
                ulonglong2 Q = *(const ulonglong2*)(Qb + 4);
                ull r0, r1;
                FADD2(r0, u[2], P.x); FADD2(r0, r0, Q.x);
                FADD2(r1, u[3], P.y); FADD2(r1, r1, Q.y);
                ob[2] = r0; ob[3] = r1;
            } else {
                ull P4 = *(const ull*)(Pb + 8);
                ull Q4 = *(const ull*)(Qb + 8);
                ull r0;
                FADD2(r0, u[4], P4); FADD2(r0, r0, Q4);
                ob[4] = r0;
            }
        }

        if (!has_next) break;
        base = nb;
        vA = nA; vB = nB; vC = nC; vD = nD;
        s = ns; d = nd2;
    }
}

// ---------------------------------------------------------------------------
extern "C" void kernel_launch(void* const* d_in, const int* in_sizes, int n_in,
                              void* d_out, int out_size) {
    const float* h   = (const float*)d_in[0];
    const float* eh  = (const float*)d_in[1];
    const float* W   = (const float*)d_in[2];
    const float* b   = (const float*)d_in[3];
    const int*   src = (const int*)d_in[4];
    const int*   dst = (const int*)d_in[5];
    float*       out = (float*)d_out;

    int n_nodes = in_sizes[0] / 128;
    int n_edges = in_sizes[4];

    proj_kernel<<<592, 128>>>(h, W, b, n_nodes);           // halves: g_P | g_Q
    edge_score_kernel<<<592, 128>>>(eh, W, src, dst, out, n_edges);
}